// round 6
// baseline (speedup 1.0000x reference)
#include <cuda_runtime.h>
#include <cuda_bf16.h>

// Shapes (fixed): B=32, D=64, N=254, L=16, H=128, P=96
#define NB 32
#define ND 64
#define NN 254
#define NL 16
#define NH 128
#define NP 96
#define PAIRS (NB*ND)          // 2048
#define XPP (NN*NL)            // 4064 floats per (b,d) pair
#define OUT_T_ELEMS (NB*NP*ND) // 196608
#define NPRE 38                // producer blocks

// ---- shared precomputed tensors (tiny) ----
__device__ __align__(16) float g_constvec[NH];
__device__ __align__(16) float g_M[NN*NL];   // M[n,l] = pos[n,:] . W_enc[l,:]
__device__ __align__(16) float g_D2[NN];     // pos[n,:] . constvec
__device__ __align__(16) float g_G[NL*NL];   // G[l',l] = W_enc[l',:] . W_enc[l,:]
__device__ __align__(16) float g_u[NL];      // W_enc[l,:] . constvec
__device__ __align__(16) float g_wb[NL];     // W_enc[l,:] . b_enc
__device__ float g_s0;                        // b_enc . constvec
__device__ int g_flag1;                       // constvec ready (monotone across replays)
__device__ int g_done;                        // precompute producers done (monotone)

__device__ __forceinline__ int ld_acq(const int* p) {
    int v;
    asm volatile("ld.acquire.gpu.global.b32 %0, [%1];" : "=r"(v) : "l"(p));
    return v;
}

// vectorized length-128 dot with 4 accumulators
__device__ __forceinline__ float dot128(const float4* __restrict__ a,
                                        const float4* __restrict__ b) {
    float s0=0.f, s1=0.f, s2=0.f, s3=0.f;
    #pragma unroll
    for (int i = 0; i < 32; i += 4) {
        float4 a0=a[i],   b0=b[i];
        float4 a1=a[i+1], b1=b[i+1];
        float4 a2=a[i+2], b2=b[i+2];
        float4 a3=a[i+3], b3=b[i+3];
        s0 += a0.x*b0.x + a0.y*b0.y + a0.z*b0.z + a0.w*b0.w;
        s1 += a1.x*b1.x + a1.y*b1.y + a1.z*b1.z + a1.w*b1.w;
        s2 += a2.x*b2.x + a2.y*b2.y + a2.z*b2.z + a2.w*b2.w;
        s3 += a3.x*b3.x + a3.y*b3.y + a3.z*b3.z + a3.w*b3.w;
    }
    return (s0+s1)+(s2+s3);
}

__global__ __launch_bounds__(128, 10)
void k_all(const float* __restrict__ x, float* __restrict__ x_copy,
           const float* __restrict__ W_enc, const float* __restrict__ b_enc,
           const float* __restrict__ pos,
           const float* __restrict__ W1, const float* __restrict__ b1,
           const float* __restrict__ W2, const float* __restrict__ b2,
           float* __restrict__ out_t) {
    __shared__ float sc[NN];                      // scores
    __shared__ __align__(16) float redq[4][NL];   // per-warp quarter reductions
    __shared__ __align__(16) float xsumS[NL];
    __shared__ __align__(16) float vS[NL];
    __shared__ __align__(16) float pooledS[NL];
    __shared__ float hdnS[NH];
    __shared__ float warpsum[4];
    __shared__ __align__(16) float red7[4][NP];   // phase-7 cross-warp partials
    __shared__ float sS, invS;

    const int tid  = threadIdx.x;
    const int pid  = blockIdx.x;
    const int lane = tid & 31;
    const int wrp  = tid >> 5;
    const int q    = tid & 3;          // l-quarter index
    const int r    = tid >> 2;         // row-within-32 index
    const float4* __restrict__ pos4 = (const float4*)pos;
    const float4* __restrict__ W4   = (const float4*)W_enc;

    // ---------- inline precompute (first NPRE blocks, wave-1 co-resident) ----------
    if (pid < NPRE) {
        if (pid == 0) {
            float a0=0.f, a1=0.f, a2=0.f, a3=0.f;
            #pragma unroll 2
            for (int n = 0; n < 252; n += 4) {
                a0 += __ldg(pos + (n+0)*NH + tid);
                a1 += __ldg(pos + (n+1)*NH + tid);
                a2 += __ldg(pos + (n+2)*NH + tid);
                a3 += __ldg(pos + (n+3)*NH + tid);
            }
            a0 += __ldg(pos + 252*NH + tid);
            a1 += __ldg(pos + 253*NH + tid);
            g_constvec[tid] = (float)NN * b_enc[tid] + ((a0+a1)+(a2+a3));
            __threadfence();
            __syncthreads();
            if (tid == 0) atomicAdd(&g_flag1, 1);
        } else if (pid <= 34) {
            int j = (pid-1)*128 + tid;
            if (j < NN*NL) {                         // M
                g_M[j] = dot128(pos4 + (j>>4)*32, W4 + (j&15)*32);
            } else if (j < NN*NL + NL*NL) {          // G
                int k = j - NN*NL;
                g_G[k] = dot128(W4 + (k>>4)*32, W4 + (k&15)*32);
            }
        } else {
            if (tid == 0) { while (ld_acq(&g_flag1) == 0) {} }
            __syncthreads();
            const float4* cv4 = (const float4*)g_constvec;
            int j = (pid-35)*128 + tid;
            if (j < NN) {                            // D2
                g_D2[j] = dot128(pos4 + j*32, cv4);
            } else if (j < NN + NL) {                // u
                g_u[j-NN] = dot128(W4 + (j-NN)*32, cv4);
            } else if (j < NN + 2*NL) {              // wb
                g_wb[j-NN-NL] = dot128(W4 + (j-NN-NL)*32, (const float4*)b_enc);
            } else if (j == NN + 2*NL) {             // s0
                g_s0 = dot128((const float4*)b_enc, cv4);
            }
        }
        __threadfence();
        __syncthreads();
        if (tid == 0) atomicAdd(&g_done, 1);
    }

    // ---------- main per-pair work (all 2048 blocks) ----------
    const float4* __restrict__ xp4 = (const float4*)(x + (size_t)pid * XPP);
    float4* __restrict__ xc4 = (float4*)(x_copy + (size_t)pid * XPP);

    // Phase 1: stream x (L1-cached) + passthrough copy + xsum partials.
    // Thread (4r+q) covers l-quarter q of rows n = it*32 + r, it = 0..7.
    float ls0=0.f, ls1=0.f, ls2=0.f, ls3=0.f;
    #pragma unroll
    for (int it = 0; it < 8; it++) {
        int i = tid + it*128;
        if (i < XPP/4) {
            float4 v = xp4[i];              // default: cache in L1 for reuse
            __stcs(xc4 + i, v);             // streaming store (no read-allocate)
            ls0 += v.x; ls1 += v.y; ls2 += v.z; ls3 += v.w;
        }
    }

    // xsum reduce: butterfly over q-classes (masks 4,8,16), then cross-warp smem
    #pragma unroll
    for (int m = 4; m <= 16; m <<= 1) {
        ls0 += __shfl_xor_sync(0xffffffffu, ls0, m);
        ls1 += __shfl_xor_sync(0xffffffffu, ls1, m);
        ls2 += __shfl_xor_sync(0xffffffffu, ls2, m);
        ls3 += __shfl_xor_sync(0xffffffffu, ls3, m);
    }
    if (lane < 4) {
        float* rr = &redq[wrp][lane*4];
        rr[0] = ls0; rr[1] = ls1; rr[2] = ls2; rr[3] = ls3;
    }
    __syncthreads();
    if (tid < NL)
        xsumS[tid] = (redq[0][tid] + redq[1][tid]) + (redq[2][tid] + redq[3][tid]);
    if (tid == 64) { while (ld_acq(&g_done) < NPRE) {} }
    __syncthreads();

    // Phase 3: v = G^T xsum + u ; s = xsum.wb + s0
    if (tid < NL) {
        float a = g_u[tid];
        #pragma unroll
        for (int lp = 0; lp < NL; lp++) a += xsumS[lp] * g_G[lp*NL + tid];
        vS[tid] = a;
    }
    if (tid == 16) {
        float a = g_s0;
        #pragma unroll
        for (int l = 0; l < NL; l++) a += xsumS[l] * g_wb[l];
        sS = a;
    }
    __syncthreads();

    // Phase 4: score[n] = s + D2[n] + x[n].v + xsum.M[n]
    // x re-read from L1; quarter partials, butterfly over lanes {^1, ^2}.
    float4 vq  = ((const float4*)vS)[q];
    float4 xsq = ((const float4*)xsumS)[q];
    float myabs = 0.f;
    float sloc = sS;
    #pragma unroll
    for (int it = 0; it < 8; it++) {
        int i = tid + it*128;
        int n = it*32 + r;
        float part = 0.f;
        if (i < XPP/4) {    // equivalent to n < NN
            float4 v = xp4[i];                               // L1 hit
            float4 m = *(const float4*)(g_M + n*NL + q*4);
            part = v.x*vq.x + v.y*vq.y + v.z*vq.z + v.w*vq.w
                 + xsq.x*m.x + xsq.y*m.y + xsq.z*m.z + xsq.w*m.w;
        }
        part += __shfl_xor_sync(0xffffffffu, part, 1);
        part += __shfl_xor_sync(0xffffffffu, part, 2);
        if (q == 0 && n < NN) {
            float a = part + sloc + g_D2[n];
            sc[n] = a;
            myabs += fabsf(a);
        }
    }
    // deterministic reduction of sum|score|
    #pragma unroll
    for (int off = 16; off; off >>= 1)
        myabs += __shfl_down_sync(0xffffffffu, myabs, off);
    if (lane == 0) warpsum[wrp] = myabs;
    __syncthreads();
    if (tid == 0)
        invS = 1.0f / ((warpsum[0] + warpsum[1]) + (warpsum[2] + warpsum[3]));
    __syncthreads();

    // Phase 5: pooled[l] = invS * sum_n x[n,l]*score[n]  (x from L1, sc smem)
    {
        float p0=0.f, p1=0.f, p2=0.f, p3=0.f;
        #pragma unroll
        for (int it = 0; it < 8; it++) {
            int i = tid + it*128;
            if (i < XPP/4) {
                float4 v = xp4[i];           // L1 hit
                float w = sc[i >> 2];
                p0 += v.x * w;
                p1 += v.y * w;
                p2 += v.z * w;
                p3 += v.w * w;
            }
        }
        #pragma unroll
        for (int m = 4; m <= 16; m <<= 1) {
            p0 += __shfl_xor_sync(0xffffffffu, p0, m);
            p1 += __shfl_xor_sync(0xffffffffu, p1, m);
            p2 += __shfl_xor_sync(0xffffffffu, p2, m);
            p3 += __shfl_xor_sync(0xffffffffu, p3, m);
        }
        if (lane < 4) {
            float* rr = &redq[wrp][lane*4];
            rr[0] = p0; rr[1] = p1; rr[2] = p2; rr[3] = p3;
        }
    }
    __syncthreads();
    if (tid < NL)
        pooledS[tid] = invS * ((redq[0][tid] + redq[1][tid]) + (redq[2][tid] + redq[3][tid]));
    __syncthreads();

    // Phase 6: hidden = leaky_relu(pooled @ W1 + b1, 0.2)   (tid = h)
    {
        float a = b1[tid];
        #pragma unroll
        for (int l = 0; l < NL; l++) a += pooledS[l] * __ldg(W1 + l*NH + tid);
        hdnS[tid] = a > 0.f ? a : 0.2f * a;
    }
    __syncthreads();

    // Phase 7: out[p] = hidden @ W2 + b2. Warp w covers h in [32w,32w+32);
    // lanes 0..23 each hold a float4 of p. Cross-warp reduce via smem.
    if (lane < 24) {
        const float4* __restrict__ W24 = (const float4*)W2;  // [h][24] float4s
        float4 acc = make_float4(0.f, 0.f, 0.f, 0.f);
        #pragma unroll 8
        for (int hh = 0; hh < 32; hh++) {
            int h = wrp*32 + hh;
            float hv = hdnS[h];
            float4 w4 = __ldg(&W24[h*24 + lane]);
            acc.x += hv*w4.x; acc.y += hv*w4.y; acc.z += hv*w4.z; acc.w += hv*w4.w;
        }
        ((float4*)red7[wrp])[lane] = acc;
    }
    __syncthreads();
    if (tid < NP) {
        float a = b2[tid] + (red7[0][tid] + red7[1][tid]) + (red7[2][tid] + red7[3][tid]);
        int b = pid >> 6, d = pid & 63;
        out_t[b*(NP*ND) + tid*ND + d] = a;
    }
}

extern "C" void kernel_launch(void* const* d_in, const int* in_sizes, int n_in,
                              void* d_out, int out_size) {
    const float* x     = (const float*)d_in[0];
    const float* W_enc = (const float*)d_in[1];
    const float* b_enc = (const float*)d_in[2];
    const float* W1    = (const float*)d_in[3];
    const float* b1    = (const float*)d_in[4];
    const float* W2    = (const float*)d_in[5];
    const float* b2    = (const float*)d_in[6];
    const float* pos   = (const float*)d_in[7];

    float* out   = (float*)d_out;          // (B,P,D) first
    float* xcopy = out + OUT_T_ELEMS;      // then p = x passthrough

    k_all<<<PAIRS, 128>>>(x, xcopy, W_enc, b_enc, pos, W1, b1, W2, b2, out);
}